// round 1
// baseline (speedup 1.0000x reference)
#include <cuda_runtime.h>

// LightSelfAttention: B=8, S=2048, D=512, fp32.
// Pipeline: QKV GEMM (NT + bias) -> scores GEMM (NT, scaled) -> masked softmax -> out GEMM (NN).

namespace {
constexpr int Bb = 8;
constexpr int Ss = 2048;
constexpr int Dd = 512;
constexpr int BM = 64, BN = 64, BK = 16, PAD = 4;
constexpr float SCALE = 0.04419417382415922f;  // 1/sqrt(512)
}

// Scratch (device globals: allocation inside kernel_launch is forbidden).
__device__ float d_Q[Bb * Ss * Dd];
__device__ float d_K[Bb * Ss * Dd];
__device__ float d_V[Bb * Ss * Dd];
__device__ float d_P[(size_t)Bb * Ss * Ss];  // scores / attn probs, 134 MB

// ---------------------------------------------------------------------------
// Kernel 1: fused QKV projection.  C = x @ W^T + b  (NT gemm, K-contig both).
// grid: (16384/64, 512/64, 3)   block: 256
// ---------------------------------------------------------------------------
__global__ void __launch_bounds__(256)
qkv_kernel(const float* __restrict__ x,
           const float* __restrict__ Wq, const float* __restrict__ bq,
           const float* __restrict__ Wk, const float* __restrict__ bk,
           const float* __restrict__ Wv, const float* __restrict__ bv)
{
    __shared__ float As[BK][BM + PAD];
    __shared__ float Bs[BK][BN + PAD];

    const float* W;
    const float* bias;
    float* C;
    if (blockIdx.z == 0)      { W = Wq; bias = bq; C = d_Q; }
    else if (blockIdx.z == 1) { W = Wk; bias = bk; C = d_K; }
    else                      { W = Wv; bias = bv; C = d_V; }

    const int m0 = blockIdx.x * BM;
    const int n0 = blockIdx.y * BN;
    const int tid = threadIdx.x;
    const int tx = tid & 15, ty = tid >> 4;
    const int rl = tid >> 2;           // 0..63: tile row this thread loads
    const int kl = (tid & 3) * 4;      // 0,4,8,12: k-offset of its float4

    float acc[4][4] = {};

    for (int k0 = 0; k0 < Dd; k0 += BK) {
        float4 va = *(const float4*)(x + (size_t)(m0 + rl) * Dd + k0 + kl);
        float4 vb = *(const float4*)(W + (size_t)(n0 + rl) * Dd + k0 + kl);
        As[kl + 0][rl] = va.x; As[kl + 1][rl] = va.y;
        As[kl + 2][rl] = va.z; As[kl + 3][rl] = va.w;
        Bs[kl + 0][rl] = vb.x; Bs[kl + 1][rl] = vb.y;
        Bs[kl + 2][rl] = vb.z; Bs[kl + 3][rl] = vb.w;
        __syncthreads();
#pragma unroll
        for (int kk = 0; kk < BK; ++kk) {
            float a[4], b[4];
            *(float4*)a = *(const float4*)&As[kk][ty * 4];
            *(float4*)b = *(const float4*)&Bs[kk][tx * 4];
#pragma unroll
            for (int i = 0; i < 4; ++i)
#pragma unroll
                for (int j = 0; j < 4; ++j)
                    acc[i][j] += a[i] * b[j];
        }
        __syncthreads();
    }

    const int n = n0 + tx * 4;
#pragma unroll
    for (int i = 0; i < 4; ++i) {
        float4 o;
        o.x = acc[i][0] + bias[n + 0];
        o.y = acc[i][1] + bias[n + 1];
        o.z = acc[i][2] + bias[n + 2];
        o.w = acc[i][3] + bias[n + 3];
        *(float4*)(C + (size_t)(m0 + ty * 4 + i) * Dd + n) = o;
    }
}

// ---------------------------------------------------------------------------
// Kernel 2: scores = (Q @ K^T) * scale, per batch (NT gemm).
// grid: (2048/64, 2048/64, 8)
// ---------------------------------------------------------------------------
__global__ void __launch_bounds__(256)
scores_kernel()
{
    __shared__ float As[BK][BM + PAD];
    __shared__ float Bs[BK][BN + PAD];

    const size_t boff = (size_t)blockIdx.z * Ss * Dd;
    const float* Q = d_Q + boff;
    const float* K = d_K + boff;
    float* C = d_P + (size_t)blockIdx.z * Ss * Ss;

    const int m0 = blockIdx.x * BM;
    const int n0 = blockIdx.y * BN;
    const int tid = threadIdx.x;
    const int tx = tid & 15, ty = tid >> 4;
    const int rl = tid >> 2;
    const int kl = (tid & 3) * 4;

    float acc[4][4] = {};

    for (int k0 = 0; k0 < Dd; k0 += BK) {
        float4 va = *(const float4*)(Q + (size_t)(m0 + rl) * Dd + k0 + kl);
        float4 vb = *(const float4*)(K + (size_t)(n0 + rl) * Dd + k0 + kl);
        As[kl + 0][rl] = va.x; As[kl + 1][rl] = va.y;
        As[kl + 2][rl] = va.z; As[kl + 3][rl] = va.w;
        Bs[kl + 0][rl] = vb.x; Bs[kl + 1][rl] = vb.y;
        Bs[kl + 2][rl] = vb.z; Bs[kl + 3][rl] = vb.w;
        __syncthreads();
#pragma unroll
        for (int kk = 0; kk < BK; ++kk) {
            float a[4], b[4];
            *(float4*)a = *(const float4*)&As[kk][ty * 4];
            *(float4*)b = *(const float4*)&Bs[kk][tx * 4];
#pragma unroll
            for (int i = 0; i < 4; ++i)
#pragma unroll
                for (int j = 0; j < 4; ++j)
                    acc[i][j] += a[i] * b[j];
        }
        __syncthreads();
    }

    const int n = n0 + tx * 4;
#pragma unroll
    for (int i = 0; i < 4; ++i) {
        float4 o;
        o.x = acc[i][0] * SCALE;
        o.y = acc[i][1] * SCALE;
        o.z = acc[i][2] * SCALE;
        o.w = acc[i][3] * SCALE;
        *(float4*)(C + (size_t)(m0 + ty * 4 + i) * Ss + n) = o;
    }
}

// ---------------------------------------------------------------------------
// Kernel 3: masked softmax over keys, in place on d_P.
// Mask is per-key (broadcast over queries): masked score -> -10000 (as in ref).
// grid: 16384 blocks (one row each), 256 threads, 8 elems/thread.
// ---------------------------------------------------------------------------
__global__ void __launch_bounds__(256)
softmax_kernel(const int* __restrict__ mask)
{
    const int row = blockIdx.x;              // 0 .. B*S-1
    const int b = row / Ss;
    float* sr = d_P + (size_t)row * Ss;
    const int* mk = mask + (size_t)b * Ss;
    const int tid = threadIdx.x;

    __shared__ float red[256];

    float vals[8];
    float lmax = -1e30f;
#pragma unroll
    for (int i = 0; i < 8; ++i) {
        const int k = tid + i * 256;
        const float v = mk[k] ? sr[k] : -10000.0f;
        vals[i] = v;
        lmax = fmaxf(lmax, v);
    }
    red[tid] = lmax;
    __syncthreads();
    for (int s = 128; s > 0; s >>= 1) {
        if (tid < s) red[tid] = fmaxf(red[tid], red[tid + s]);
        __syncthreads();
    }
    const float m = red[0];
    __syncthreads();

    float lsum = 0.0f;
#pragma unroll
    for (int i = 0; i < 8; ++i) {
        vals[i] = __expf(vals[i] - m);
        lsum += vals[i];
    }
    red[tid] = lsum;
    __syncthreads();
    for (int s = 128; s > 0; s >>= 1) {
        if (tid < s) red[tid] += red[tid + s];
        __syncthreads();
    }
    const float rinv = 1.0f / red[0];
#pragma unroll
    for (int i = 0; i < 8; ++i)
        sr[tid + i * 256] = vals[i] * rinv;
}

// ---------------------------------------------------------------------------
// Kernel 4: out = attn @ V, per batch (NN gemm: A K-contig, B N-contig).
// grid: (2048/64, 512/64, 8)
// ---------------------------------------------------------------------------
__global__ void __launch_bounds__(256)
out_kernel(float* __restrict__ out)
{
    __shared__ float As[BK][BM + PAD];
    __shared__ float Bs[BK][BN + PAD];

    const float* A = d_P + (size_t)blockIdx.z * Ss * Ss;
    const float* V = d_V + (size_t)blockIdx.z * Ss * Dd;
    float* C = out + (size_t)blockIdx.z * Ss * Dd;

    const int m0 = blockIdx.x * BM;
    const int n0 = blockIdx.y * BN;
    const int tid = threadIdx.x;
    const int tx = tid & 15, ty = tid >> 4;
    const int rl = tid >> 2;           // A loader: row 0..63
    const int kl = (tid & 3) * 4;      // A loader: k-offset
    const int rb = tid >> 4;           // B loader: k-row 0..15
    const int nb = (tid & 15) * 4;     // B loader: n-offset

    float acc[4][4] = {};

    for (int k0 = 0; k0 < Ss; k0 += BK) {
        float4 va = *(const float4*)(A + (size_t)(m0 + rl) * Ss + k0 + kl);
        As[kl + 0][rl] = va.x; As[kl + 1][rl] = va.y;
        As[kl + 2][rl] = va.z; As[kl + 3][rl] = va.w;
        float4 vb = *(const float4*)(V + (size_t)(k0 + rb) * Dd + n0 + nb);
        *(float4*)&Bs[rb][nb] = vb;
        __syncthreads();
#pragma unroll
        for (int kk = 0; kk < BK; ++kk) {
            float a[4], b[4];
            *(float4*)a = *(const float4*)&As[kk][ty * 4];
            *(float4*)b = *(const float4*)&Bs[kk][tx * 4];
#pragma unroll
            for (int i = 0; i < 4; ++i)
#pragma unroll
                for (int j = 0; j < 4; ++j)
                    acc[i][j] += a[i] * b[j];
        }
        __syncthreads();
    }

    const int n = n0 + tx * 4;
#pragma unroll
    for (int i = 0; i < 4; ++i)
        *(float4*)(C + (size_t)(m0 + ty * 4 + i) * Dd + n) =
            make_float4(acc[i][0], acc[i][1], acc[i][2], acc[i][3]);
}

// ---------------------------------------------------------------------------
extern "C" void kernel_launch(void* const* d_in, const int* in_sizes, int n_in,
                              void* d_out, int out_size)
{
    (void)in_sizes; (void)n_in; (void)out_size;
    const float* x  = (const float*)d_in[0];
    const int*   mk = (const int*)d_in[1];
    const float* Wq = (const float*)d_in[2];
    const float* bq = (const float*)d_in[3];
    const float* Wk = (const float*)d_in[4];
    const float* bk = (const float*)d_in[5];
    const float* Wv = (const float*)d_in[6];
    const float* bv = (const float*)d_in[7];
    float* out = (float*)d_out;

    dim3 g1(Bb * Ss / BM, Dd / BN, 3);       // 256 x 8 x 3
    qkv_kernel<<<g1, 256>>>(x, Wq, bq, Wk, bk, Wv, bv);

    dim3 g2(Ss / BM, Ss / BN, Bb);           // 32 x 32 x 8
    scores_kernel<<<g2, 256>>>();

    softmax_kernel<<<Bb * Ss, 256>>>(mk);    // 16384 rows

    dim3 g3(Ss / BM, Dd / BN, Bb);           // 32 x 8 x 8
    out_kernel<<<g3, 256>>>(out);
}

// round 3
// speedup vs baseline: 1.3650x; 1.3650x over previous
#include <cuda_runtime.h>

// LightSelfAttention: B=8, S=2048, D=512, fp32.
// QKV GEMM (NT + bias) -> scores GEMM (NT, scaled) -> masked softmax -> out GEMM (NN).
// R3 == R2 resubmit (infra failure last round): 128x128 tiles, 8x8 micro-tiles,
// BK=8, smem double buffering with register-staged global prefetch.

namespace {
constexpr int Bb = 8;
constexpr int Ss = 2048;
constexpr int Dd = 512;
constexpr int BM = 128, BN = 128, BK = 8, PAD = 4;
constexpr float SCALE = 0.04419417382415922f;  // 1/sqrt(512)
}

// Scratch (device globals: allocation inside kernel_launch is forbidden).
__device__ float d_Q[Bb * Ss * Dd];
__device__ float d_K[Bb * Ss * Dd];
__device__ float d_V[Bb * Ss * Dd];
__device__ float d_P[(size_t)Bb * Ss * Ss];  // scores / attn probs, 134 MB

// ---------------------------------------------------------------------------
// 256 threads per block; thread (tx,ty) owns rows {ty*4+i, 64+ty*4+i} x cols
// {tx*4+j, 64+tx*4+j} of the 128x128 C tile.
// ---------------------------------------------------------------------------

#define GEMM_COMPUTE_TILE(AS, BS)                                              \
    _Pragma("unroll")                                                          \
    for (int kk = 0; kk < BK; ++kk) {                                          \
        float a8[8], b8[8];                                                    \
        *(float4*)&a8[0] = *(const float4*)&AS[kk][ty * 4];                    \
        *(float4*)&a8[4] = *(const float4*)&AS[kk][64 + ty * 4];               \
        *(float4*)&b8[0] = *(const float4*)&BS[kk][tx * 4];                    \
        *(float4*)&b8[4] = *(const float4*)&BS[kk][64 + tx * 4];               \
        _Pragma("unroll")                                                      \
        for (int i = 0; i < 8; ++i)                                            \
            _Pragma("unroll")                                                  \
            for (int j = 0; j < 8; ++j)                                        \
                acc[i][j] += a8[i] * b8[j];                                    \
    }

// Scatter a float4 of K-contiguous values into transposed smem tile.
#define STORE_A_T(BUFBASE, V)                                                  \
    do {                                                                       \
        BUFBASE[kl + 0][rl] = (V).x; BUFBASE[kl + 1][rl] = (V).y;              \
        BUFBASE[kl + 2][rl] = (V).z; BUFBASE[kl + 3][rl] = (V).w;              \
    } while (0)

// ---------------------------------------------------------------------------
// Kernel 1: fused QKV projection.  C = x @ W^T + b   (NT, both K-contig).
// grid: (128, 4, 3)  block: 256
// ---------------------------------------------------------------------------
__global__ void __launch_bounds__(256, 2)
qkv_kernel(const float* __restrict__ x,
           const float* __restrict__ Wq, const float* __restrict__ bq,
           const float* __restrict__ Wk, const float* __restrict__ bk,
           const float* __restrict__ Wv, const float* __restrict__ bv)
{
    __shared__ float As[2][BK][BM + PAD];
    __shared__ float Bs[2][BK][BN + PAD];

    const float* W;  const float* bias;  float* C;
    if (blockIdx.z == 0)      { W = Wq; bias = bq; C = d_Q; }
    else if (blockIdx.z == 1) { W = Wk; bias = bk; C = d_K; }
    else                      { W = Wv; bias = bv; C = d_V; }

    const int m0 = blockIdx.x * BM;
    const int n0 = blockIdx.y * BN;
    const int tid = threadIdx.x;
    const int tx = tid & 15, ty = tid >> 4;
    const int rl = tid >> 1;            // 0..127: row this thread loads
    const int kl = (tid & 1) * 4;       // 0 or 4

    const float* Arow = x + (size_t)(m0 + rl) * Dd + kl;
    const float* Brow = W + (size_t)(n0 + rl) * Dd + kl;

    float acc[8][8] = {};

    float4 va = *(const float4*)(Arow);
    float4 vb = *(const float4*)(Brow);
    STORE_A_T(As[0], va);
    STORE_A_T(Bs[0], vb);
    __syncthreads();

    const int nk = Dd / BK;
    for (int t = 0; t < nk - 1; ++t) {
        const int buf = t & 1;
        va = *(const float4*)(Arow + (t + 1) * BK);
        vb = *(const float4*)(Brow + (t + 1) * BK);
        GEMM_COMPUTE_TILE(As[buf], Bs[buf]);
        STORE_A_T(As[buf ^ 1], va);
        STORE_A_T(Bs[buf ^ 1], vb);
        __syncthreads();
    }
    GEMM_COMPUTE_TILE(As[(nk - 1) & 1], Bs[(nk - 1) & 1]);

#pragma unroll
    for (int qi = 0; qi < 2; ++qi)
#pragma unroll
        for (int qj = 0; qj < 2; ++qj) {
            const int n = n0 + qj * 64 + tx * 4;
            const float4 bv4 = *(const float4*)(bias + n);
#pragma unroll
            for (int i = 0; i < 4; ++i) {
                const int r = qi * 4 + i;
                float4 o;
                o.x = acc[r][qj * 4 + 0] + bv4.x;
                o.y = acc[r][qj * 4 + 1] + bv4.y;
                o.z = acc[r][qj * 4 + 2] + bv4.z;
                o.w = acc[r][qj * 4 + 3] + bv4.w;
                *(float4*)(C + (size_t)(m0 + qi * 64 + ty * 4 + i) * Dd + n) = o;
            }
        }
}

// ---------------------------------------------------------------------------
// Kernel 2: scores = (Q @ K^T) * scale, per batch (NT).
// grid: (16, 16, 8)
// ---------------------------------------------------------------------------
__global__ void __launch_bounds__(256, 2)
scores_kernel()
{
    __shared__ float As[2][BK][BM + PAD];
    __shared__ float Bs[2][BK][BN + PAD];

    const size_t boff = (size_t)blockIdx.z * Ss * Dd;
    const float* Q = d_Q + boff;
    const float* K = d_K + boff;
    float* C = d_P + (size_t)blockIdx.z * Ss * Ss;

    const int m0 = blockIdx.x * BM;
    const int n0 = blockIdx.y * BN;
    const int tid = threadIdx.x;
    const int tx = tid & 15, ty = tid >> 4;
    const int rl = tid >> 1;
    const int kl = (tid & 1) * 4;

    const float* Arow = Q + (size_t)(m0 + rl) * Dd + kl;
    const float* Brow = K + (size_t)(n0 + rl) * Dd + kl;

    float acc[8][8] = {};

    float4 va = *(const float4*)(Arow);
    float4 vb = *(const float4*)(Brow);
    STORE_A_T(As[0], va);
    STORE_A_T(Bs[0], vb);
    __syncthreads();

    const int nk = Dd / BK;
    for (int t = 0; t < nk - 1; ++t) {
        const int buf = t & 1;
        va = *(const float4*)(Arow + (t + 1) * BK);
        vb = *(const float4*)(Brow + (t + 1) * BK);
        GEMM_COMPUTE_TILE(As[buf], Bs[buf]);
        STORE_A_T(As[buf ^ 1], va);
        STORE_A_T(Bs[buf ^ 1], vb);
        __syncthreads();
    }
    GEMM_COMPUTE_TILE(As[(nk - 1) & 1], Bs[(nk - 1) & 1]);

#pragma unroll
    for (int qi = 0; qi < 2; ++qi)
#pragma unroll
        for (int qj = 0; qj < 2; ++qj) {
            const int n = n0 + qj * 64 + tx * 4;
#pragma unroll
            for (int i = 0; i < 4; ++i) {
                const int r = qi * 4 + i;
                float4 o;
                o.x = acc[r][qj * 4 + 0] * SCALE;
                o.y = acc[r][qj * 4 + 1] * SCALE;
                o.z = acc[r][qj * 4 + 2] * SCALE;
                o.w = acc[r][qj * 4 + 3] * SCALE;
                *(float4*)(C + (size_t)(m0 + qi * 64 + ty * 4 + i) * Ss + n) = o;
            }
        }
}

// ---------------------------------------------------------------------------
// Kernel 3: masked softmax over keys, in place on d_P. Mask is per-key.
// grid: 16384 blocks (one row each), 256 threads, 8 elems/thread.
// ---------------------------------------------------------------------------
__global__ void __launch_bounds__(256)
softmax_kernel(const int* __restrict__ mask)
{
    const int row = blockIdx.x;
    const int b = row >> 11;             // row / 2048
    float* sr = d_P + (size_t)row * Ss;
    const int* mk = mask + (size_t)b * Ss;
    const int tid = threadIdx.x;

    __shared__ float red[256];

    float vals[8];
    float lmax = -1e30f;
#pragma unroll
    for (int i = 0; i < 8; ++i) {
        const int k = tid + i * 256;
        const float v = mk[k] ? sr[k] : -10000.0f;
        vals[i] = v;
        lmax = fmaxf(lmax, v);
    }
    red[tid] = lmax;
    __syncthreads();
    for (int s = 128; s > 16; s >>= 1) {
        if (tid < s) red[tid] = fmaxf(red[tid], red[tid + s]);
        __syncthreads();
    }
    if (tid < 32) {
        float v = red[tid];
#pragma unroll
        for (int off = 16; off > 0; off >>= 1)
            v = fmaxf(v, __shfl_xor_sync(0xffffffffu, v, off));
        red[tid] = v;
    }
    __syncthreads();
    const float m = red[0];

    float lsum = 0.0f;
#pragma unroll
    for (int i = 0; i < 8; ++i) {
        vals[i] = __expf(vals[i] - m);
        lsum += vals[i];
    }
    __syncthreads();
    red[tid] = lsum;
    __syncthreads();
    for (int s = 128; s > 16; s >>= 1) {
        if (tid < s) red[tid] += red[tid + s];
        __syncthreads();
    }
    if (tid < 32) {
        float v = red[tid];
#pragma unroll
        for (int off = 16; off > 0; off >>= 1)
            v += __shfl_xor_sync(0xffffffffu, v, off);
        red[tid] = v;
    }
    __syncthreads();
    const float rinv = 1.0f / red[0];
#pragma unroll
    for (int i = 0; i < 8; ++i)
        sr[tid + i * 256] = vals[i] * rinv;
}

// ---------------------------------------------------------------------------
// Kernel 4: out = attn @ V, per batch (NN: A K-contig, B N-contig).
// grid: (16, 4, 8)
// ---------------------------------------------------------------------------
__global__ void __launch_bounds__(256, 2)
out_kernel(float* __restrict__ out)
{
    __shared__ float As[2][BK][BM + PAD];
    __shared__ float Bs[2][BK][BN + PAD];

    const float* A = d_P + (size_t)blockIdx.z * Ss * Ss;
    const float* V = d_V + (size_t)blockIdx.z * Ss * Dd;
    float* C = out + (size_t)blockIdx.z * Ss * Dd;

    const int m0 = blockIdx.x * BM;
    const int n0 = blockIdx.y * BN;
    const int tid = threadIdx.x;
    const int tx = tid & 15, ty = tid >> 4;
    const int rl = tid >> 1;            // A loader: row 0..127
    const int kl = (tid & 1) * 4;       // A loader: k-offset 0/4
    const int rb = tid >> 5;            // B loader: k-row 0..7
    const int nb = (tid & 31) * 4;      // B loader: n-offset

    const float* Arow = A + (size_t)(m0 + rl) * Ss + kl;
    const float* Brow = V + (size_t)rb * Dd + n0 + nb;

    float acc[8][8] = {};

    float4 va = *(const float4*)(Arow);
    float4 vb = *(const float4*)(Brow);
    STORE_A_T(As[0], va);
    *(float4*)&Bs[0][rb][nb] = vb;
    __syncthreads();

    const int nk = Ss / BK;
    for (int t = 0; t < nk - 1; ++t) {
        const int buf = t & 1;
        va = *(const float4*)(Arow + (t + 1) * BK);
        vb = *(const float4*)(Brow + (size_t)(t + 1) * BK * Dd);
        GEMM_COMPUTE_TILE(As[buf], Bs[buf]);
        STORE_A_T(As[buf ^ 1], va);
        *(float4*)&Bs[buf ^ 1][rb][nb] = vb;
        __syncthreads();
    }
    GEMM_COMPUTE_TILE(As[(nk - 1) & 1], Bs[(nk - 1) & 1]);

#pragma unroll
    for (int qi = 0; qi < 2; ++qi)
#pragma unroll
        for (int qj = 0; qj < 2; ++qj) {
            const int n = n0 + qj * 64 + tx * 4;
#pragma unroll
            for (int i = 0; i < 4; ++i) {
                const int r = qi * 4 + i;
                *(float4*)(C + (size_t)(m0 + qi * 64 + ty * 4 + i) * Dd + n) =
                    make_float4(acc[r][qj * 4 + 0], acc[r][qj * 4 + 1],
                                acc[r][qj * 4 + 2], acc[r][qj * 4 + 3]);
            }
        }
}

// ---------------------------------------------------------------------------
extern "C" void kernel_launch(void* const* d_in, const int* in_sizes, int n_in,
                              void* d_out, int out_size)
{
    (void)in_sizes; (void)n_in; (void)out_size;
    const float* x  = (const float*)d_in[0];
    const int*   mk = (const int*)d_in[1];
    const float* Wq = (const float*)d_in[2];
    const float* bq = (const float*)d_in[3];
    const float* Wk = (const float*)d_in[4];
    const float* bk = (const float*)d_in[5];
    const float* Wv = (const float*)d_in[6];
    const float* bv = (const float*)d_in[7];
    float* out = (float*)d_out;

    dim3 g1(Bb * Ss / BM, Dd / BN, 3);       // 128 x 4 x 3
    qkv_kernel<<<g1, 256>>>(x, Wq, bq, Wk, bk, Wv, bv);

    dim3 g2(Ss / BM, Ss / BN, Bb);           // 16 x 16 x 8
    scores_kernel<<<g2, 256>>>();

    softmax_kernel<<<Bb * Ss, 256>>>(mk);    // 16384 rows

    dim3 g3(Ss / BM, Dd / BN, Bb);           // 16 x 4 x 8
    out_kernel<<<g3, 256>>>(out);
}

// round 9
// speedup vs baseline: 2.2538x; 1.6511x over previous
#include <cuda_runtime.h>
#include <cuda_bf16.h>
#include <cstdint>

// LightSelfAttention B=8,S=2048,D=512 fp32.
// tcgen05 is NOT available in this build (ptxas targets plain sm_103), so the
// GEMMs use the legacy tensor-core path: mma.sync m16n8k16 bf16 (HMMA) with a
// 3-pass hi/lo bf16 split for fp32-level accuracy.
// split(x),split(W) -> QKV gemm (emits Qhi/lo,Khi/lo + V fp32)
// -> V transpose+split -> scores gemm -> softmax (emits Phi/lo) -> out gemm.
// R9 == R6 resubmit (GPU acquisition timeouts; kernel still unbenched).

namespace {
constexpr int Bb = 8, Ss = 2048, Dd = 512;
constexpr float SCALE = 0.04419417382415922f;  // 1/sqrt(512)
constexpr int BM = 128, BN = 128, BK = 32;     // block tile (bf16 K)
constexpr int RS = 40;                          // smem row stride (bf16), pad 8
constexpr int TILE_B  = 128 * RS * 2;           // 10240 B per operand tile
constexpr int STAGE_B = 4 * TILE_B;             // Ah,Al,Bh,Bl = 40960 B
constexpr int SMEM_B  = 2 * STAGE_B;            // 81920 B (double buffered)
}

// ---------------- device scratch (allocation is forbidden) ------------------
__device__ __align__(256) __nv_bfloat16 d_xh[(size_t)Bb * Ss * Dd];
__device__ __align__(256) __nv_bfloat16 d_xl[(size_t)Bb * Ss * Dd];
__device__ __align__(256) __nv_bfloat16 d_Wh[3 * Dd * Dd];
__device__ __align__(256) __nv_bfloat16 d_Wl[3 * Dd * Dd];
__device__ __align__(256) __nv_bfloat16 d_Qh[(size_t)Bb * Ss * Dd];
__device__ __align__(256) __nv_bfloat16 d_Ql[(size_t)Bb * Ss * Dd];
__device__ __align__(256) __nv_bfloat16 d_Kh[(size_t)Bb * Ss * Dd];
__device__ __align__(256) __nv_bfloat16 d_Kl[(size_t)Bb * Ss * Dd];
__device__ __align__(256) float         d_V [(size_t)Bb * Ss * Dd];
__device__ __align__(256) __nv_bfloat16 d_Vth[(size_t)Bb * Dd * Ss];  // V^T
__device__ __align__(256) __nv_bfloat16 d_Vtl[(size_t)Bb * Dd * Ss];
__device__ __align__(256) float         d_P [(size_t)Bb * Ss * Ss];   // scores
__device__ __align__(256) __nv_bfloat16 d_Ph[(size_t)Bb * Ss * Ss];   // probs
__device__ __align__(256) __nv_bfloat16 d_Pl[(size_t)Bb * Ss * Ss];

// ---------------- PTX helpers ----------------------------------------------
__device__ __forceinline__ uint32_t smem_u32(const void* p) {
    uint32_t a;
    asm("{ .reg .u64 t; cvta.to.shared.u64 t, %1; cvt.u32.u64 %0, t; }"
        : "=r"(a) : "l"(p));
    return a;
}
__device__ __forceinline__ void cpa16(uint32_t dst, const void* src) {
    asm volatile("cp.async.cg.shared.global [%0], [%1], 16;"
                 :: "r"(dst), "l"(src) : "memory");
}
__device__ __forceinline__ void cp_commit() {
    asm volatile("cp.async.commit_group;" ::: "memory");
}
template <int N>
__device__ __forceinline__ void cp_wait() {
    asm volatile("cp.async.wait_group %0;" :: "n"(N) : "memory");
}
__device__ __forceinline__ void ldsm_x4(uint32_t& r0, uint32_t& r1,
                                        uint32_t& r2, uint32_t& r3, uint32_t a) {
    asm volatile("ldmatrix.sync.aligned.m8n8.x4.shared.b16 {%0,%1,%2,%3}, [%4];"
                 : "=r"(r0), "=r"(r1), "=r"(r2), "=r"(r3) : "r"(a));
}
__device__ __forceinline__ void mma_bf16(float c[4], const uint32_t a[4],
                                         const uint32_t b[2]) {
    asm volatile(
        "mma.sync.aligned.m16n8k16.row.col.f32.bf16.bf16.f32 "
        "{%0,%1,%2,%3}, {%4,%5,%6,%7}, {%8,%9}, {%0,%1,%2,%3};"
        : "+f"(c[0]), "+f"(c[1]), "+f"(c[2]), "+f"(c[3])
        : "r"(a[0]), "r"(a[1]), "r"(a[2]), "r"(a[3]), "r"(b[0]), "r"(b[1]));
}
__device__ __forceinline__ uint32_t pack_bf16(float a, float b) {
    __nv_bfloat162 t;
    t.x = __float2bfloat16(a);
    t.y = __float2bfloat16(b);
    return *(uint32_t*)&t;
}

// ---------------- stage loader: Ah,Al,Bh,Bl (128 rows x 32 bf16 each) -------
__device__ __forceinline__ void issue_stage(
    uint32_t sb, int stage,
    const __nv_bfloat16* a0, const __nv_bfloat16* a1, int ldA,
    const __nv_bfloat16* b0, const __nv_bfloat16* b1, int ldB, int tid)
{
#pragma unroll
    for (int c = 0; c < 2; ++c) {
        const int idx = tid * 2 + c;
        const int row = idx >> 2, q = idx & 3;
        const uint32_t soff = sb + stage * STAGE_B + (row * RS + q * 8) * 2;
        const size_t goA = (size_t)row * ldA + q * 8;
        const size_t goB = (size_t)row * ldB + q * 8;
        cpa16(soff,              a0 + goA);
        cpa16(soff + TILE_B,     a1 + goA);
        cpa16(soff + 2 * TILE_B, b0 + goB);
        cpa16(soff + 3 * TILE_B, b1 + goB);
    }
    cp_commit();
}

// ---------------- GEMM core: 3-pass split, acc[mi][ni][4] per thread --------
__device__ __forceinline__ void gemm_core(
    const __nv_bfloat16* __restrict__ Ah, const __nv_bfloat16* __restrict__ Al, int ldA,
    const __nv_bfloat16* __restrict__ Bh, const __nv_bfloat16* __restrict__ Bl, int ldB,
    int ktiles, char* smem, float acc[4][4][4])
{
    const int tid = threadIdx.x, lane = tid & 31, warp = tid >> 5;
    const int wm = warp & 1, wn = warp >> 1;   // 2 x 4 warp grid
    const uint32_t sb = smem_u32(smem);

    issue_stage(sb, 0, Ah, Al, ldA, Bh, Bl, ldB, tid);

    for (int t = 0; t < ktiles; ++t) {
        const int stage = t & 1;
        if (t + 1 < ktiles) {
            const int o = (t + 1) * BK;
            issue_stage(sb, stage ^ 1, Ah + o, Al + o, ldA, Bh + o, Bl + o, ldB, tid);
            cp_wait<1>();
        } else {
            cp_wait<0>();
        }
        __syncthreads();

        const uint32_t base = sb + stage * STAGE_B;
#pragma unroll
        for (int kk = 0; kk < 2; ++kk) {
            const int k0 = kk * 16;
            uint32_t ahf[4][4], alf[4][4], bhf[4][2], blf[4][2];
#pragma unroll
            for (int mi = 0; mi < 4; ++mi) {
                const int row = wm * 64 + mi * 16 + (lane & 15);
                const uint32_t a = base + (row * RS + k0 + (lane >> 4) * 8) * 2;
                ldsm_x4(ahf[mi][0], ahf[mi][1], ahf[mi][2], ahf[mi][3], a);
                ldsm_x4(alf[mi][0], alf[mi][1], alf[mi][2], alf[mi][3], a + TILE_B);
            }
#pragma unroll
            for (int np = 0; np < 2; ++np) {
                const int nrow = wn * 32 + np * 16 + (lane >> 4) * 8 + (lane & 7);
                const int kcol = k0 + ((lane >> 3) & 1) * 8;
                const uint32_t a = base + 2 * TILE_B + (nrow * RS + kcol) * 2;
                ldsm_x4(bhf[np * 2][0], bhf[np * 2][1],
                        bhf[np * 2 + 1][0], bhf[np * 2 + 1][1], a);
                ldsm_x4(blf[np * 2][0], blf[np * 2][1],
                        blf[np * 2 + 1][0], blf[np * 2 + 1][1], a + TILE_B);
            }
#pragma unroll
            for (int mi = 0; mi < 4; ++mi)
#pragma unroll
                for (int ni = 0; ni < 4; ++ni) {
                    mma_bf16(acc[mi][ni], ahf[mi], bhf[ni]);
                    mma_bf16(acc[mi][ni], ahf[mi], blf[ni]);
                    mma_bf16(acc[mi][ni], alf[mi], bhf[ni]);
                }
        }
        __syncthreads();
    }
}

// ---------------- split fp32 -> bf16 hi/lo ----------------------------------
__global__ void __launch_bounds__(256)
split_kernel(const float* __restrict__ src, int sel, int n4) {
    const int i = blockIdx.x * 256 + threadIdx.x;
    if (i >= n4) return;
    __nv_bfloat16 *hi, *lo;
    if (sel == 0) { hi = d_xh; lo = d_xl; }
    else { hi = d_Wh + (size_t)(sel - 1) * Dd * Dd;
           lo = d_Wl + (size_t)(sel - 1) * Dd * Dd; }
    const float4 v = ((const float4*)src)[i];
    const float f[4] = {v.x, v.y, v.z, v.w};
    __nv_bfloat16 h[4], l[4];
#pragma unroll
    for (int j = 0; j < 4; ++j) {
        h[j] = __float2bfloat16(f[j]);
        l[j] = __float2bfloat16(f[j] - __bfloat162float(h[j]));
    }
    ((uint2*)hi)[i] = *(const uint2*)h;
    ((uint2*)lo)[i] = *(const uint2*)l;
}

// ---------------- kernel 1: QKV gemm (x @ W^T + b) --------------------------
__global__ void __launch_bounds__(256, 1)
qkv_gemm(const float* __restrict__ bq, const float* __restrict__ bk,
         const float* __restrict__ bv) {
    extern __shared__ char smem[];
    const int z = blockIdx.z;
    const int m0 = blockIdx.x * BM, n0 = blockIdx.y * BN;
    const size_t woff = (size_t)z * Dd * Dd + (size_t)n0 * Dd;

    float acc[4][4][4] = {};
    gemm_core(d_xh + (size_t)m0 * Dd, d_xl + (size_t)m0 * Dd, Dd,
              d_Wh + woff, d_Wl + woff, Dd, Dd / BK, smem, acc);

    const float* bias = (z == 0) ? bq : (z == 1) ? bk : bv;
    const int lane = threadIdx.x & 31, warp = threadIdx.x >> 5;
    const int wm = warp & 1, wn = warp >> 1;
    const int rbase = m0 + wm * 64 + (lane >> 2);
    const int cbase = n0 + wn * 32 + (lane & 3) * 2;

#pragma unroll
    for (int mi = 0; mi < 4; ++mi)
#pragma unroll
        for (int ni = 0; ni < 4; ++ni) {
            const int r = rbase + mi * 16;
            const int c = cbase + ni * 8;
            const float b0 = bias[c], b1 = bias[c + 1];
            const float v00 = acc[mi][ni][0] + b0, v01 = acc[mi][ni][1] + b1;
            const float v10 = acc[mi][ni][2] + b0, v11 = acc[mi][ni][3] + b1;
            if (z == 2) {
                *(float2*)(d_V + (size_t)r * Dd + c)       = make_float2(v00, v01);
                *(float2*)(d_V + (size_t)(r + 8) * Dd + c) = make_float2(v10, v11);
            } else {
                __nv_bfloat16* dh = ((z == 0) ? d_Qh : d_Kh);
                __nv_bfloat16* dl = ((z == 0) ? d_Ql : d_Kl);
                const float h00 = __bfloat162float(__float2bfloat16(v00));
                const float h01 = __bfloat162float(__float2bfloat16(v01));
                const float h10 = __bfloat162float(__float2bfloat16(v10));
                const float h11 = __bfloat162float(__float2bfloat16(v11));
                *(uint32_t*)(dh + (size_t)r * Dd + c)       = pack_bf16(v00, v01);
                *(uint32_t*)(dl + (size_t)r * Dd + c)       = pack_bf16(v00 - h00, v01 - h01);
                *(uint32_t*)(dh + (size_t)(r + 8) * Dd + c) = pack_bf16(v10, v11);
                *(uint32_t*)(dl + (size_t)(r + 8) * Dd + c) = pack_bf16(v10 - h10, v11 - h11);
            }
        }
}

// ---------------- kernel 2: V transpose + split -----------------------------
__global__ void __launch_bounds__(256)
vtrans_kernel() {
    __shared__ float tile[32][33];
    const int b = blockIdx.z;
    const int s0 = blockIdx.x * 32, d0 = blockIdx.y * 32;
    const int tx = threadIdx.x, ty = threadIdx.y;
    const float* src = d_V + (size_t)b * Ss * Dd;
#pragma unroll
    for (int i = ty; i < 32; i += 8)
        tile[i][tx] = src[(size_t)(s0 + i) * Dd + d0 + tx];
    __syncthreads();
    __nv_bfloat16* th = d_Vth + (size_t)b * Dd * Ss;
    __nv_bfloat16* tl = d_Vtl + (size_t)b * Dd * Ss;
#pragma unroll
    for (int i = ty; i < 32; i += 8) {
        const float v = tile[tx][i];
        const __nv_bfloat16 h = __float2bfloat16(v);
        th[(size_t)(d0 + i) * Ss + s0 + tx] = h;
        tl[(size_t)(d0 + i) * Ss + s0 + tx] = __float2bfloat16(v - __bfloat162float(h));
    }
}

// ---------------- kernel 3: scores gemm (Q @ K^T * scale) -------------------
__global__ void __launch_bounds__(256, 1)
scores_gemm() {
    extern __shared__ char smem[];
    const int b = blockIdx.z;
    const int m0 = blockIdx.x * BM, n0 = blockIdx.y * BN;
    const size_t off = (size_t)b * Ss * Dd;

    float acc[4][4][4] = {};
    gemm_core(d_Qh + off + (size_t)m0 * Dd, d_Ql + off + (size_t)m0 * Dd, Dd,
              d_Kh + off + (size_t)n0 * Dd, d_Kl + off + (size_t)n0 * Dd, Dd,
              Dd / BK, smem, acc);

    const int lane = threadIdx.x & 31, warp = threadIdx.x >> 5;
    const int wm = warp & 1, wn = warp >> 1;
    const int rbase = m0 + wm * 64 + (lane >> 2);
    const int cbase = n0 + wn * 32 + (lane & 3) * 2;
    float* C = d_P + (size_t)b * Ss * Ss;

#pragma unroll
    for (int mi = 0; mi < 4; ++mi)
#pragma unroll
        for (int ni = 0; ni < 4; ++ni) {
            const int r = rbase + mi * 16;
            const int c = cbase + ni * 8;
            *(float2*)(C + (size_t)r * Ss + c) =
                make_float2(acc[mi][ni][0] * SCALE, acc[mi][ni][1] * SCALE);
            *(float2*)(C + (size_t)(r + 8) * Ss + c) =
                make_float2(acc[mi][ni][2] * SCALE, acc[mi][ni][3] * SCALE);
        }
}

// ---------------- kernel 4: masked softmax -> P hi/lo -----------------------
__global__ void __launch_bounds__(256)
softmax_kernel(const int* __restrict__ mask) {
    const int row = blockIdx.x;
    const int b = row >> 11;
    const float* sr = d_P + (size_t)row * Ss;
    const int* mk = mask + (size_t)b * Ss;
    const int tid = threadIdx.x;

    __shared__ float red[256];

    float vals[8];
    float lmax = -1e30f;
#pragma unroll
    for (int i = 0; i < 8; ++i) {
        const int k = tid + i * 256;
        const float v = mk[k] ? sr[k] : -10000.0f;
        vals[i] = v;
        lmax = fmaxf(lmax, v);
    }
    red[tid] = lmax;
    __syncthreads();
    for (int s = 128; s > 16; s >>= 1) {
        if (tid < s) red[tid] = fmaxf(red[tid], red[tid + s]);
        __syncthreads();
    }
    if (tid < 32) {
        float v = red[tid];
#pragma unroll
        for (int off = 16; off > 0; off >>= 1)
            v = fmaxf(v, __shfl_xor_sync(0xffffffffu, v, off));
        red[tid] = v;
    }
    __syncthreads();
    const float m = red[0];

    float lsum = 0.0f;
#pragma unroll
    for (int i = 0; i < 8; ++i) {
        vals[i] = __expf(vals[i] - m);
        lsum += vals[i];
    }
    __syncthreads();
    red[tid] = lsum;
    __syncthreads();
    for (int s = 128; s > 16; s >>= 1) {
        if (tid < s) red[tid] += red[tid + s];
        __syncthreads();
    }
    if (tid < 32) {
        float v = red[tid];
#pragma unroll
        for (int off = 16; off > 0; off >>= 1)
            v += __shfl_xor_sync(0xffffffffu, v, off);
        red[tid] = v;
    }
    __syncthreads();
    const float rinv = 1.0f / red[0];

    __nv_bfloat16* ph = d_Ph + (size_t)row * Ss;
    __nv_bfloat16* pl = d_Pl + (size_t)row * Ss;
#pragma unroll
    for (int i = 0; i < 8; ++i) {
        const int k = tid + i * 256;
        const float p = vals[i] * rinv;
        const __nv_bfloat16 h = __float2bfloat16(p);
        ph[k] = h;
        pl[k] = __float2bfloat16(p - __bfloat162float(h));
    }
}

// ---------------- kernel 5: out gemm (P @ V) --------------------------------
__global__ void __launch_bounds__(256, 1)
out_gemm(float* __restrict__ out) {
    extern __shared__ char smem[];
    const int b = blockIdx.z;
    const int m0 = blockIdx.x * BM, n0 = blockIdx.y * BN;

    float acc[4][4][4] = {};
    gemm_core(d_Ph + (size_t)b * Ss * Ss + (size_t)m0 * Ss,
              d_Pl + (size_t)b * Ss * Ss + (size_t)m0 * Ss, Ss,
              d_Vth + (size_t)b * Dd * Ss + (size_t)n0 * Ss,
              d_Vtl + (size_t)b * Dd * Ss + (size_t)n0 * Ss, Ss,
              Ss / BK, smem, acc);

    const int lane = threadIdx.x & 31, warp = threadIdx.x >> 5;
    const int wm = warp & 1, wn = warp >> 1;
    const int rbase = m0 + wm * 64 + (lane >> 2);
    const int cbase = n0 + wn * 32 + (lane & 3) * 2;
    float* C = out + (size_t)b * Ss * Dd;

#pragma unroll
    for (int mi = 0; mi < 4; ++mi)
#pragma unroll
        for (int ni = 0; ni < 4; ++ni) {
            const int r = rbase + mi * 16;
            const int c = cbase + ni * 8;
            *(float2*)(C + (size_t)r * Dd + c) =
                make_float2(acc[mi][ni][0], acc[mi][ni][1]);
            *(float2*)(C + (size_t)(r + 8) * Dd + c) =
                make_float2(acc[mi][ni][2], acc[mi][ni][3]);
        }
}

// ---------------------------------------------------------------------------
extern "C" void kernel_launch(void* const* d_in, const int* in_sizes, int n_in,
                              void* d_out, int out_size) {
    (void)in_sizes; (void)n_in; (void)out_size;
    const float* x  = (const float*)d_in[0];
    const int*   mk = (const int*)d_in[1];
    const float* Wq = (const float*)d_in[2];
    const float* bq = (const float*)d_in[3];
    const float* Wk = (const float*)d_in[4];
    const float* bk = (const float*)d_in[5];
    const float* Wv = (const float*)d_in[6];
    const float* bv = (const float*)d_in[7];
    float* out = (float*)d_out;

    cudaFuncSetAttribute(qkv_gemm, cudaFuncAttributeMaxDynamicSharedMemorySize, SMEM_B);
    cudaFuncSetAttribute(scores_gemm, cudaFuncAttributeMaxDynamicSharedMemorySize, SMEM_B);
    cudaFuncSetAttribute(out_gemm, cudaFuncAttributeMaxDynamicSharedMemorySize, SMEM_B);

    const int nx4 = Bb * Ss * Dd / 4;
    const int nw4 = Dd * Dd / 4;
    split_kernel<<<(nx4 + 255) / 256, 256>>>(x, 0, nx4);
    split_kernel<<<(nw4 + 255) / 256, 256>>>(Wq, 1, nw4);
    split_kernel<<<(nw4 + 255) / 256, 256>>>(Wk, 2, nw4);
    split_kernel<<<(nw4 + 255) / 256, 256>>>(Wv, 3, nw4);

    qkv_gemm<<<dim3(Bb * Ss / BM, Dd / BN, 3), 256, SMEM_B>>>(bq, bk, bv);

    vtrans_kernel<<<dim3(Ss / 32, Dd / 32, Bb), dim3(32, 8)>>>();

    scores_gemm<<<dim3(Ss / BM, Ss / BN, Bb), 256, SMEM_B>>>();

    softmax_kernel<<<Bb * Ss, 256>>>(mk);

    out_gemm<<<dim3(Ss / BM, Dd / BN, Bb), 256, SMEM_B>>>(out);
}

// round 11
// speedup vs baseline: 3.1142x; 1.3818x over previous
#include <cuda_runtime.h>
#include <cuda_bf16.h>
#include <cstdint>

// LightSelfAttention B=8,S=2048,D=512 fp32.
// mma.sync m16n8k16 bf16 (HMMA) with 3-pass hi/lo split (fp32-level accuracy).
// R11 == R10 resubmit (GPU acquisition timeout): mask compaction — masked keys
// have prob exactly 0 (exp(-10000-m) underflows in fp32, same as the
// reference), so K/V are scattered into compacted rows and the scores/out
// GEMMs run over ~half the keys.

namespace {
constexpr int Bb = 8, Ss = 2048, Dd = 512;
constexpr float SCALE = 0.04419417382415922f;  // 1/sqrt(512)
constexpr int BM = 128, BN = 128, BK = 32;     // block tile (bf16 K)
constexpr int RS = 40;                          // smem row stride (bf16), pad 8
constexpr int TILE_B  = 128 * RS * 2;           // 10240 B per operand tile
constexpr int STAGE_B = 4 * TILE_B;             // Ah,Al,Bh,Bl = 40960 B
constexpr int SMEM_B  = 2 * STAGE_B;            // 81920 B (double buffered)
}

// ---------------- device scratch (allocation is forbidden) ------------------
__device__ __align__(256) __nv_bfloat16 d_xh[(size_t)Bb * Ss * Dd];
__device__ __align__(256) __nv_bfloat16 d_xl[(size_t)Bb * Ss * Dd];
__device__ __align__(256) __nv_bfloat16 d_Wh[3 * Dd * Dd];
__device__ __align__(256) __nv_bfloat16 d_Wl[3 * Dd * Dd];
__device__ __align__(256) __nv_bfloat16 d_Qh[(size_t)Bb * Ss * Dd];
__device__ __align__(256) __nv_bfloat16 d_Ql[(size_t)Bb * Ss * Dd];
__device__ __align__(256) __nv_bfloat16 d_Kh[(size_t)Bb * Ss * Dd];  // compacted
__device__ __align__(256) __nv_bfloat16 d_Kl[(size_t)Bb * Ss * Dd];  // compacted
__device__ __align__(256) float         d_V [(size_t)Bb * Ss * Dd];  // compacted
__device__ __align__(256) __nv_bfloat16 d_Vth[(size_t)Bb * Dd * Ss]; // V^T compact
__device__ __align__(256) __nv_bfloat16 d_Vtl[(size_t)Bb * Dd * Ss];
__device__ __align__(256) float         d_P [(size_t)Bb * Ss * Ss];  // scores
__device__ __align__(256) __nv_bfloat16 d_Ph[(size_t)Bb * Ss * Ss];  // probs
__device__ __align__(256) __nv_bfloat16 d_Pl[(size_t)Bb * Ss * Ss];
// mask compaction state
__device__ int d_cpos[Bb * Ss];   // orig key -> compact pos (-1 if masked)
__device__ int d_nb[Bb];          // unmasked count
__device__ int d_nbpad[Bb];       // padded to 256
__device__ int d_allm[Bb];        // all-masked flag

// ---------------- PTX helpers ----------------------------------------------
__device__ __forceinline__ uint32_t smem_u32(const void* p) {
    uint32_t a;
    asm("{ .reg .u64 t; cvta.to.shared.u64 t, %1; cvt.u32.u64 %0, t; }"
        : "=r"(a) : "l"(p));
    return a;
}
__device__ __forceinline__ void cpa16(uint32_t dst, const void* src) {
    asm volatile("cp.async.cg.shared.global [%0], [%1], 16;"
                 :: "r"(dst), "l"(src) : "memory");
}
__device__ __forceinline__ void cp_commit() {
    asm volatile("cp.async.commit_group;" ::: "memory");
}
template <int N>
__device__ __forceinline__ void cp_wait() {
    asm volatile("cp.async.wait_group %0;" :: "n"(N) : "memory");
}
__device__ __forceinline__ void ldsm_x4(uint32_t& r0, uint32_t& r1,
                                        uint32_t& r2, uint32_t& r3, uint32_t a) {
    asm volatile("ldmatrix.sync.aligned.m8n8.x4.shared.b16 {%0,%1,%2,%3}, [%4];"
                 : "=r"(r0), "=r"(r1), "=r"(r2), "=r"(r3) : "r"(a));
}
__device__ __forceinline__ void mma_bf16(float c[4], const uint32_t a[4],
                                         const uint32_t b[2]) {
    asm volatile(
        "mma.sync.aligned.m16n8k16.row.col.f32.bf16.bf16.f32 "
        "{%0,%1,%2,%3}, {%4,%5,%6,%7}, {%8,%9}, {%0,%1,%2,%3};"
        : "+f"(c[0]), "+f"(c[1]), "+f"(c[2]), "+f"(c[3])
        : "r"(a[0]), "r"(a[1]), "r"(a[2]), "r"(a[3]), "r"(b[0]), "r"(b[1]));
}
__device__ __forceinline__ uint32_t pack_bf16(float a, float b) {
    __nv_bfloat162 t;
    t.x = __float2bfloat16(a);
    t.y = __float2bfloat16(b);
    return *(uint32_t*)&t;
}

// ---------------- mask compaction: prefix scan per batch --------------------
__global__ void __launch_bounds__(256)
compact_kernel(const int* __restrict__ mask) {
    const int b = blockIdx.x, tid = threadIdx.x;
    const int lane = tid & 31, warp = tid >> 5;
    const int* mk = mask + (size_t)b * Ss;

    int m[8];
    int c = 0;
#pragma unroll
    for (int i = 0; i < 8; ++i) { m[i] = mk[tid * 8 + i] ? 1 : 0; c += m[i]; }

    int sc = c;  // inclusive warp scan of chunk counts
#pragma unroll
    for (int off = 1; off < 32; off <<= 1) {
        int v = __shfl_up_sync(0xffffffffu, sc, off);
        if (lane >= off) sc += v;
    }
    __shared__ int wsum[8], woff[8];
    if (lane == 31) wsum[warp] = sc;
    __syncthreads();
    if (tid == 0) {
        int acc = 0;
        for (int w = 0; w < 8; ++w) { woff[w] = acc; acc += wsum[w]; }
        d_nb[b] = acc ? acc : Ss;
        d_nbpad[b] = acc ? ((acc + 255) & ~255) : Ss;
        d_allm[b] = (acc == 0);
    }
    __syncthreads();
    const int allm = d_allm[b];
    int pos = sc - c + woff[warp];  // exclusive prefix of this chunk
#pragma unroll
    for (int i = 0; i < 8; ++i) {
        const int s = tid * 8 + i;
        const int dest = allm ? s : (m[i] ? pos : -1);
        pos += m[i];
        d_cpos[b * Ss + s] = dest;
    }
}

// ---------------- stage loader: Ah,Al,Bh,Bl (128 rows x 32 bf16 each) -------
__device__ __forceinline__ void issue_stage(
    uint32_t sb, int stage,
    const __nv_bfloat16* a0, const __nv_bfloat16* a1, int ldA,
    const __nv_bfloat16* b0, const __nv_bfloat16* b1, int ldB, int tid)
{
#pragma unroll
    for (int c = 0; c < 2; ++c) {
        const int idx = tid * 2 + c;
        const int row = idx >> 2, q = idx & 3;
        const uint32_t soff = sb + stage * STAGE_B + (row * RS + q * 8) * 2;
        const size_t goA = (size_t)row * ldA + q * 8;
        const size_t goB = (size_t)row * ldB + q * 8;
        cpa16(soff,              a0 + goA);
        cpa16(soff + TILE_B,     a1 + goA);
        cpa16(soff + 2 * TILE_B, b0 + goB);
        cpa16(soff + 3 * TILE_B, b1 + goB);
    }
    cp_commit();
}

// ---------------- GEMM core: 3-pass split, acc[mi][ni][4] per thread --------
__device__ __forceinline__ void gemm_core(
    const __nv_bfloat16* __restrict__ Ah, const __nv_bfloat16* __restrict__ Al, int ldA,
    const __nv_bfloat16* __restrict__ Bh, const __nv_bfloat16* __restrict__ Bl, int ldB,
    int ktiles, char* smem, float acc[4][4][4])
{
    const int tid = threadIdx.x, lane = tid & 31, warp = tid >> 5;
    const int wm = warp & 1, wn = warp >> 1;   // 2 x 4 warp grid
    const uint32_t sb = smem_u32(smem);

    issue_stage(sb, 0, Ah, Al, ldA, Bh, Bl, ldB, tid);

    for (int t = 0; t < ktiles; ++t) {
        const int stage = t & 1;
        if (t + 1 < ktiles) {
            const int o = (t + 1) * BK;
            issue_stage(sb, stage ^ 1, Ah + o, Al + o, ldA, Bh + o, Bl + o, ldB, tid);
            cp_wait<1>();
        } else {
            cp_wait<0>();
        }
        __syncthreads();

        const uint32_t base = sb + stage * STAGE_B;
#pragma unroll
        for (int kk = 0; kk < 2; ++kk) {
            const int k0 = kk * 16;
            uint32_t ahf[4][4], alf[4][4], bhf[4][2], blf[4][2];
#pragma unroll
            for (int mi = 0; mi < 4; ++mi) {
                const int row = wm * 64 + mi * 16 + (lane & 15);
                const uint32_t a = base + (row * RS + k0 + (lane >> 4) * 8) * 2;
                ldsm_x4(ahf[mi][0], ahf[mi][1], ahf[mi][2], ahf[mi][3], a);
                ldsm_x4(alf[mi][0], alf[mi][1], alf[mi][2], alf[mi][3], a + TILE_B);
            }
#pragma unroll
            for (int np = 0; np < 2; ++np) {
                const int nrow = wn * 32 + np * 16 + (lane >> 4) * 8 + (lane & 7);
                const int kcol = k0 + ((lane >> 3) & 1) * 8;
                const uint32_t a = base + 2 * TILE_B + (nrow * RS + kcol) * 2;
                ldsm_x4(bhf[np * 2][0], bhf[np * 2][1],
                        bhf[np * 2 + 1][0], bhf[np * 2 + 1][1], a);
                ldsm_x4(blf[np * 2][0], blf[np * 2][1],
                        blf[np * 2 + 1][0], blf[np * 2 + 1][1], a + TILE_B);
            }
#pragma unroll
            for (int mi = 0; mi < 4; ++mi)
#pragma unroll
                for (int ni = 0; ni < 4; ++ni) {
                    mma_bf16(acc[mi][ni], ahf[mi], bhf[ni]);
                    mma_bf16(acc[mi][ni], ahf[mi], blf[ni]);
                    mma_bf16(acc[mi][ni], alf[mi], bhf[ni]);
                }
        }
        __syncthreads();
    }
}

// ---------------- split fp32 -> bf16 hi/lo ----------------------------------
__global__ void __launch_bounds__(256)
split_kernel(const float* __restrict__ src, int sel, int n4) {
    const int i = blockIdx.x * 256 + threadIdx.x;
    if (i >= n4) return;
    __nv_bfloat16 *hi, *lo;
    if (sel == 0) { hi = d_xh; lo = d_xl; }
    else { hi = d_Wh + (size_t)(sel - 1) * Dd * Dd;
           lo = d_Wl + (size_t)(sel - 1) * Dd * Dd; }
    const float4 v = ((const float4*)src)[i];
    const float f[4] = {v.x, v.y, v.z, v.w};
    __nv_bfloat16 h[4], l[4];
#pragma unroll
    for (int j = 0; j < 4; ++j) {
        h[j] = __float2bfloat16(f[j]);
        l[j] = __float2bfloat16(f[j] - __bfloat162float(h[j]));
    }
    ((uint2*)hi)[i] = *(const uint2*)h;
    ((uint2*)lo)[i] = *(const uint2*)l;
}

// ---------------- kernel 1: QKV gemm (x @ W^T + b) --------------------------
// Q written dense; K, V scattered to compacted rows via d_cpos.
__global__ void __launch_bounds__(256, 1)
qkv_gemm(const float* __restrict__ bq, const float* __restrict__ bk,
         const float* __restrict__ bv) {
    extern __shared__ char smem[];
    const int z = blockIdx.z;
    const int m0 = blockIdx.x * BM, n0 = blockIdx.y * BN;
    const size_t woff = (size_t)z * Dd * Dd + (size_t)n0 * Dd;

    float acc[4][4][4] = {};
    gemm_core(d_xh + (size_t)m0 * Dd, d_xl + (size_t)m0 * Dd, Dd,
              d_Wh + woff, d_Wl + woff, Dd, Dd / BK, smem, acc);

    const float* bias = (z == 0) ? bq : (z == 1) ? bk : bv;
    const int lane = threadIdx.x & 31, warp = threadIdx.x >> 5;
    const int wm = warp & 1, wn = warp >> 1;
    const int rbase = m0 + wm * 64 + (lane >> 2);
    const int cbase = n0 + wn * 32 + (lane & 3) * 2;

#pragma unroll
    for (int mi = 0; mi < 4; ++mi) {
        const int r = rbase + mi * 16;
        int dst1 = r, dst2 = r + 8;        // dense rows for Q
        bool w1 = true, w2 = true;
        if (z != 0) {                       // compacted rows for K, V
            const int bb = r >> 11;
            const int p1 = d_cpos[bb * Ss + (r & 2047)];
            const int p2 = d_cpos[bb * Ss + ((r + 8) & 2047)];
            w1 = p1 >= 0; w2 = p2 >= 0;
            dst1 = bb * Ss + p1;
            dst2 = bb * Ss + p2;
        }
#pragma unroll
        for (int ni = 0; ni < 4; ++ni) {
            const int c = cbase + ni * 8;
            const float b0 = bias[c], b1 = bias[c + 1];
            const float v00 = acc[mi][ni][0] + b0, v01 = acc[mi][ni][1] + b1;
            const float v10 = acc[mi][ni][2] + b0, v11 = acc[mi][ni][3] + b1;
            if (z == 2) {
                if (w1) *(float2*)(d_V + (size_t)dst1 * Dd + c) = make_float2(v00, v01);
                if (w2) *(float2*)(d_V + (size_t)dst2 * Dd + c) = make_float2(v10, v11);
            } else {
                __nv_bfloat16* dh = ((z == 0) ? d_Qh : d_Kh);
                __nv_bfloat16* dl = ((z == 0) ? d_Ql : d_Kl);
                const float h00 = __bfloat162float(__float2bfloat16(v00));
                const float h01 = __bfloat162float(__float2bfloat16(v01));
                const float h10 = __bfloat162float(__float2bfloat16(v10));
                const float h11 = __bfloat162float(__float2bfloat16(v11));
                if (w1) {
                    *(uint32_t*)(dh + (size_t)dst1 * Dd + c) = pack_bf16(v00, v01);
                    *(uint32_t*)(dl + (size_t)dst1 * Dd + c) = pack_bf16(v00 - h00, v01 - h01);
                }
                if (w2) {
                    *(uint32_t*)(dh + (size_t)dst2 * Dd + c) = pack_bf16(v10, v11);
                    *(uint32_t*)(dl + (size_t)dst2 * Dd + c) = pack_bf16(v10 - h10, v11 - h11);
                }
            }
        }
    }
}

// ---------------- kernel 2: V transpose + split (compact, zero pad) ---------
__global__ void __launch_bounds__(256)
vtrans_kernel() {
    __shared__ float tile[32][33];
    const int b = blockIdx.z;
    const int s0 = blockIdx.x * 32, d0 = blockIdx.y * 32;
    if (s0 >= d_nbpad[b]) return;
    const int nb = d_nb[b];
    const int tx = threadIdx.x, ty = threadIdx.y;
    const float* src = d_V + (size_t)b * Ss * Dd;
#pragma unroll
    for (int i = ty; i < 32; i += 8)
        tile[i][tx] = (s0 + i < nb) ? src[(size_t)(s0 + i) * Dd + d0 + tx] : 0.0f;
    __syncthreads();
    __nv_bfloat16* th = d_Vth + (size_t)b * Dd * Ss;
    __nv_bfloat16* tl = d_Vtl + (size_t)b * Dd * Ss;
#pragma unroll
    for (int i = ty; i < 32; i += 8) {
        const float v = tile[tx][i];
        const __nv_bfloat16 h = __float2bfloat16(v);
        th[(size_t)(d0 + i) * Ss + s0 + tx] = h;
        tl[(size_t)(d0 + i) * Ss + s0 + tx] = __float2bfloat16(v - __bfloat162float(h));
    }
}

// ---------------- kernel 3: scores gemm (Q @ Kc^T * scale, N = nbpad) -------
__global__ void __launch_bounds__(256, 1)
scores_gemm() {
    const int b = blockIdx.z;
    const int n0 = blockIdx.y * BN;
    if (n0 >= d_nbpad[b]) return;
    extern __shared__ char smem[];
    const int m0 = blockIdx.x * BM;
    const size_t off = (size_t)b * Ss * Dd;

    float acc[4][4][4] = {};
    gemm_core(d_Qh + off + (size_t)m0 * Dd, d_Ql + off + (size_t)m0 * Dd, Dd,
              d_Kh + off + (size_t)n0 * Dd, d_Kl + off + (size_t)n0 * Dd, Dd,
              Dd / BK, smem, acc);

    const int lane = threadIdx.x & 31, warp = threadIdx.x >> 5;
    const int wm = warp & 1, wn = warp >> 1;
    const int rbase = m0 + wm * 64 + (lane >> 2);
    const int cbase = n0 + wn * 32 + (lane & 3) * 2;
    float* C = d_P + (size_t)b * Ss * Ss;

#pragma unroll
    for (int mi = 0; mi < 4; ++mi)
#pragma unroll
        for (int ni = 0; ni < 4; ++ni) {
            const int r = rbase + mi * 16;
            const int c = cbase + ni * 8;
            *(float2*)(C + (size_t)r * Ss + c) =
                make_float2(acc[mi][ni][0] * SCALE, acc[mi][ni][1] * SCALE);
            *(float2*)(C + (size_t)(r + 8) * Ss + c) =
                make_float2(acc[mi][ni][2] * SCALE, acc[mi][ni][3] * SCALE);
        }
}

// ---------------- kernel 4: softmax over compact keys -> P hi/lo ------------
__global__ void __launch_bounds__(256)
softmax_kernel() {
    const int row = blockIdx.x;
    const int b = row >> 11;
    const int tid = threadIdx.x;
    __nv_bfloat16* ph = d_Ph + (size_t)row * Ss;
    __nv_bfloat16* pl = d_Pl + (size_t)row * Ss;

    if (d_allm[b]) {  // all keys masked: uniform probs over all 2048 keys
        const __nv_bfloat16 u = __float2bfloat16(1.0f / 2048.0f);  // exact
        const __nv_bfloat16 zz = __float2bfloat16(0.0f);
        for (int j = tid; j < Ss; j += 256) { ph[j] = u; pl[j] = zz; }
        return;
    }

    const int nb = d_nb[b];
    const int nbp = d_nbpad[b];
    const int niter = nbp >> 8;
    const float* sr = d_P + (size_t)row * Ss;

    __shared__ float red[256];
    float vals[8];
    float lmax = -1e30f;
    for (int it = 0; it < niter; ++it) {
        const int j = tid + it * 256;
        const float v = (j < nb) ? sr[j] : -__int_as_float(0x7f800000);  // -inf pad
        vals[it] = v;
        lmax = fmaxf(lmax, v);
    }
    red[tid] = lmax;
    __syncthreads();
    for (int s = 128; s > 16; s >>= 1) {
        if (tid < s) red[tid] = fmaxf(red[tid], red[tid + s]);
        __syncthreads();
    }
    if (tid < 32) {
        float v = red[tid];
#pragma unroll
        for (int off = 16; off > 0; off >>= 1)
            v = fmaxf(v, __shfl_xor_sync(0xffffffffu, v, off));
        red[tid] = v;
    }
    __syncthreads();
    const float m = red[0];

    float lsum = 0.0f;
    for (int it = 0; it < niter; ++it) {
        vals[it] = __expf(vals[it] - m);   // pads -> exp(-inf) = 0
        lsum += vals[it];
    }
    __syncthreads();
    red[tid] = lsum;
    __syncthreads();
    for (int s = 128; s > 16; s >>= 1) {
        if (tid < s) red[tid] += red[tid + s];
        __syncthreads();
    }
    if (tid < 32) {
        float v = red[tid];
#pragma unroll
        for (int off = 16; off > 0; off >>= 1)
            v += __shfl_xor_sync(0xffffffffu, v, off);
        red[tid] = v;
    }
    __syncthreads();
    const float rinv = 1.0f / red[0];

    for (int it = 0; it < niter; ++it) {
        const int j = tid + it * 256;
        const float p = vals[it] * rinv;
        const __nv_bfloat16 h = __float2bfloat16(p);
        ph[j] = h;
        pl[j] = __float2bfloat16(p - __bfloat162float(h));
    }
}

// ---------------- kernel 5: out gemm (Pc @ Vc, K = nbpad) -------------------
__global__ void __launch_bounds__(256, 1)
out_gemm(float* __restrict__ out) {
    extern __shared__ char smem[];
    const int b = blockIdx.z;
    const int m0 = blockIdx.x * BM, n0 = blockIdx.y * BN;
    const int ktiles = d_nbpad[b] >> 5;  // nbpad / BK

    float acc[4][4][4] = {};
    gemm_core(d_Ph + (size_t)b * Ss * Ss + (size_t)m0 * Ss,
              d_Pl + (size_t)b * Ss * Ss + (size_t)m0 * Ss, Ss,
              d_Vth + (size_t)b * Dd * Ss + (size_t)n0 * Ss,
              d_Vtl + (size_t)b * Dd * Ss + (size_t)n0 * Ss, Ss,
              ktiles, smem, acc);

    const int lane = threadIdx.x & 31, warp = threadIdx.x >> 5;
    const int wm = warp & 1, wn = warp >> 1;
    const int rbase = m0 + wm * 64 + (lane >> 2);
    const int cbase = n0 + wn * 32 + (lane & 3) * 2;
    float* C = out + (size_t)b * Ss * Dd;

#pragma unroll
    for (int mi = 0; mi < 4; ++mi)
#pragma unroll
        for (int ni = 0; ni < 4; ++ni) {
            const int r = rbase + mi * 16;
            const int c = cbase + ni * 8;
            *(float2*)(C + (size_t)r * Dd + c) =
                make_float2(acc[mi][ni][0], acc[mi][ni][1]);
            *(float2*)(C + (size_t)(r + 8) * Dd + c) =
                make_float2(acc[mi][ni][2], acc[mi][ni][3]);
        }
}

// ---------------------------------------------------------------------------
extern "C" void kernel_launch(void* const* d_in, const int* in_sizes, int n_in,
                              void* d_out, int out_size) {
    (void)in_sizes; (void)n_in; (void)out_size;
    const float* x  = (const float*)d_in[0];
    const int*   mk = (const int*)d_in[1];
    const float* Wq = (const float*)d_in[2];
    const float* bq = (const float*)d_in[3];
    const float* Wk = (const float*)d_in[4];
    const float* bk = (const float*)d_in[5];
    const float* Wv = (const float*)d_in[6];
    const float* bv = (const float*)d_in[7];
    float* out = (float*)d_out;

    cudaFuncSetAttribute(qkv_gemm, cudaFuncAttributeMaxDynamicSharedMemorySize, SMEM_B);
    cudaFuncSetAttribute(scores_gemm, cudaFuncAttributeMaxDynamicSharedMemorySize, SMEM_B);
    cudaFuncSetAttribute(out_gemm, cudaFuncAttributeMaxDynamicSharedMemorySize, SMEM_B);

    compact_kernel<<<Bb, 256>>>(mk);

    const int nx4 = Bb * Ss * Dd / 4;
    const int nw4 = Dd * Dd / 4;
    split_kernel<<<(nx4 + 255) / 256, 256>>>(x, 0, nx4);
    split_kernel<<<(nw4 + 255) / 256, 256>>>(Wq, 1, nw4);
    split_kernel<<<(nw4 + 255) / 256, 256>>>(Wk, 2, nw4);
    split_kernel<<<(nw4 + 255) / 256, 256>>>(Wv, 3, nw4);

    qkv_gemm<<<dim3(Bb * Ss / BM, Dd / BN, 3), 256, SMEM_B>>>(bq, bk, bv);

    vtrans_kernel<<<dim3(Ss / 32, Dd / 32, Bb), dim3(32, 8)>>>();

    scores_gemm<<<dim3(Ss / BM, Ss / BN, Bb), 256, SMEM_B>>>();

    softmax_kernel<<<Bb * Ss, 256>>>();

    out_gemm<<<dim3(Ss / BM, Dd / BN, Bb), 256, SMEM_B>>>(out);
}